// round 16
// baseline (speedup 1.0000x reference)
#include <cuda_runtime.h>

typedef unsigned long long u64;

// ---- packed f32x2 primitives ----
__device__ __forceinline__ u64 pk2(float lo, float hi) {
    u64 r;
    asm("mov.b64 %0, {%1, %2};" : "=l"(r)
        : "r"(__float_as_uint(lo)), "r"(__float_as_uint(hi)));
    return r;
}
__device__ __forceinline__ void upk2(float& lo, float& hi, u64 v) {
    unsigned a, b;
    asm("mov.b64 {%0, %1}, %2;" : "=r"(a), "=r"(b) : "l"(v));
    lo = __uint_as_float(a); hi = __uint_as_float(b);
}
__device__ __forceinline__ u64 fma2_(u64 a, u64 b, u64 c) {
    u64 d;
    asm("fma.rn.f32x2 %0, %1, %2, %3;" : "=l"(d) : "l"(a), "l"(b), "l"(c));
    return d;
}
__device__ __forceinline__ u64 mul2_(u64 a, u64 b) {
    u64 d;
    asm("mul.rn.f32x2 %0, %1, %2;" : "=l"(d) : "l"(a), "l"(b));
    return d;
}
__device__ __forceinline__ u64 swap2(u64 v) {
    float lo, hi; upk2(lo, hi, v); return pk2(hi, lo);
}

// Inter-kernel feature buffer: [B=128][784]
__device__ float g_feat[128 * 784];

// Row coefficients for a split gate. U = [[a+ib, c+id],[-c+id, a-ib]], own row
// rho; fold=true composes a post-CNOT row swap (output taken from row 1-rho,
// expressed as alpha*mine + beta*partner).
__device__ __forceinline__ void rowcoef(float a, float b, float c, float d,
                                        int rho, bool fold,
                                        float& ar, float& ai, float& br, float& bi) {
    if (!fold) {
        if (rho == 0) { ar = a;  ai = b;  br = c;  bi = d; }
        else          { ar = a;  ai = -b; br = -c; bi = d; }
    } else {
        if (rho == 0) { ar = -c; ai = d;  br = a;  bi = -b; }
        else          { ar = c;  ai = d;  br = a;  bi = b; }
    }
}

// ============================ Kernel A: circuit ============================
// 8 threads per patch. Lane bits within an octet: r1=(sub>>2)&1 -> qubit 1,
// r2=(sub>>1)&1 -> qubit 2, r3=sub&1 -> qubit 3. Pack halves = qubit 0
// (lo: b0=0, hi: b0=1). State per thread: zr, zi (one u64 each).
__global__ __launch_bounds__(512, 3)
void qcirc_kernel(const float* __restrict__ x,       // [B,1,28,28]
                  const float* __restrict__ weight,  // [60]
                  int total_patches)                  // B*196
{
    __shared__ float4 g[20];
    __shared__ u64 cG0[4][2][6];   // q0 gate (pack dim), X30 pre-fold by r3
    __shared__ u64 cG1[4][2][6];   // q1 gate (xor 4), row r1; X01 fold on HI half
    __shared__ u64 cG2[4][4][6];   // q2 gate (xor 2), [r1*2+r2]; X12 fold when r1
    __shared__ u64 cG3[4][4][6];   // q3 gate (xor 1), [r2*2+r3]; X23 fold when r2

    const int tid = threadIdx.x;

    // ---- fused SU(2) gates U = Ry(p2)*Rz(p1)*Ry(p0)
    if (tid < 20) {
        const int L = tid >> 2, q = tid & 3;
        const float* p = weight + 12 * L;
        float ca, sa, cb, sb, cc, sc;
        sincosf(0.5f * p[q],     &sa, &ca);
        sincosf(0.5f * p[4 + q], &sb, &cb);
        sincosf(0.5f * p[8 + q], &sc, &cc);
        float t0 = cc * ca - sc * sa;
        float t1 = cc * ca + sc * sa;
        float t2 = cc * sa + sc * ca;
        float t3 = cc * sa - sc * ca;
        g[tid] = make_float4(cb * t0, -sb * t1, -cb * t2, sb * t3);
    }
    __syncthreads();

    // ---- coefficient banks (rings fully folded)
    if (tid < 8) {
        // cG0[li][r3]: generic 2x2 [[p+iq, r+is],[t+iu, v+iw]] intra-pack bank.
        // r3=1: pre-composed X30 = column swap.
        const int li = tid >> 1, r3 = tid & 1;
        float4 G = g[(li + 1) * 4 + 0];
        float a = G.x, bb = G.y, c = G.z, d = G.w;
        float p, q, r, s, t, u, v, w;
        if (r3 == 0) { p = a; q = bb; r = c; s = d;  t = -c; u = d;   v = a;  w = -bb; }
        else         { p = c; q = d;  r = a; s = bb; t = a;  u = -bb; v = -c; w = d; }
        u64* o = cG0[li][r3];
        o[0] = pk2(p, v);    o[1] = pk2(-q, -w);  o[2] = pk2(r, t);
        o[3] = pk2(-s, -u);  o[4] = pk2(q, w);    o[5] = pk2(s, u);
    } else if (tid < 16) {
        // cG1[li][r1]: lo half = plain row r1; hi half = X01-folded (layers 1..3)
        const int idx = tid - 8, li = idx >> 1, r1 = idx & 1;
        float4 G = g[(li + 1) * 4 + 1];
        float aL, iL, bL, dL, aH, iH, bH, dH;
        rowcoef(G.x, G.y, G.z, G.w, r1, false, aL, iL, bL, dL);
        rowcoef(G.x, G.y, G.z, G.w, r1, li < 3, aH, iH, bH, dH);
        u64* o = cG1[li][r1];
        o[0] = pk2(aL, aH);   o[1] = pk2(-iL, -iH); o[2] = pk2(iL, iH);
        o[3] = pk2(bL, bH);   o[4] = pk2(-dL, -dH); o[5] = pk2(dL, dH);
    } else if (tid < 32) {
        // cG2[li][r1*2+r2]: X12 fold (row swap) when r1=1, layers 1..3
        const int idx = tid - 16, li = idx >> 2, rr = idx & 3;
        const int r1 = rr >> 1, r2 = rr & 1;
        float4 G = g[(li + 1) * 4 + 2];
        float ar, ai, br, bi;
        rowcoef(G.x, G.y, G.z, G.w, r2, (r1 != 0) && (li < 3), ar, ai, br, bi);
        u64* o = cG2[li][rr];
        o[0] = pk2(ar, ar);   o[1] = pk2(-ai, -ai); o[2] = pk2(ai, ai);
        o[3] = pk2(br, br);   o[4] = pk2(-bi, -bi); o[5] = pk2(bi, bi);
    } else if (tid < 48) {
        // cG3[li][r2*2+r3]: X23 fold when r2=1, layers 1..3
        const int idx = tid - 32, li = idx >> 2, rr = idx & 3;
        const int r2 = rr >> 1, r3 = rr & 1;
        float4 G = g[(li + 1) * 4 + 3];
        float ar, ai, br, bi;
        rowcoef(G.x, G.y, G.z, G.w, r3, (r2 != 0) && (li < 3), ar, ai, br, bi);
        u64* o = cG3[li][rr];
        o[0] = pk2(ar, ar);   o[1] = pk2(-ai, -ai); o[2] = pk2(ai, ai);
        o[3] = pk2(br, br);   o[4] = pk2(-bi, -bi); o[5] = pk2(bi, bi);
    }
    __syncthreads();

    // ---- per-thread patch assignment
    const int gp_raw = blockIdx.x * 64 + (tid >> 3);
    const bool valid = gp_raw < total_patches;
    const int gp  = valid ? gp_raw : total_patches - 1;
    const int sub = tid & 7;
    const int r1 = (sub >> 2) & 1;
    const int r2 = (sub >> 1) & 1;
    const int r3 = sub & 1;

    const int bimg = gp / 196;
    const int p    = gp - bimg * 196;
    const int pi_ = p / 14, pj = p % 14;
    const float* xb = x + bimg * 784 + (2 * pi_) * 28 + 2 * pj;
    const float2 xr0 = *reinterpret_cast<const float2*>(xb);
    const float2 xr1 = *reinterpret_cast<const float2*>(xb + 28);
    const float ang[4] = { xr0.x, xr0.y, xr1.x, xr1.y };

    // ---- layer 0 fused with Rx encoding on |0000>, ring-0 twist:
    // amp(b0,b1,b2,b3) = A(b0) B(b0^b1) C(b1^b2) D(b2^b3)
    const float PI = 3.14159265358979323846f;
    float A0r, A0i, A1r, A1i, B0r, B0i, B1r, B1i, Cr, Ci, Dr, Di;
    {
        const int ic = r1 ^ r2, id_ = r2 ^ r3;
#pragma unroll
        for (int q = 0; q < 4; q++) {
            float sx, cx;
            __sincosf(PI * ang[q], &sx, &cx);
            float4 G = g[q];
            float a0r =  G.x * cx + G.w * sx;
            float a0i =  G.y * cx - G.z * sx;
            float a1r = -(G.z * cx + G.y * sx);
            float a1i =  G.w * cx - G.x * sx;
            if (q == 0)      { A0r = a0r; A0i = a0i; A1r = a1r; A1i = a1i; }
            else if (q == 1) { B0r = a0r; B0i = a0i; B1r = a1r; B1i = a1i; }
            else if (q == 2) { Cr = ic ? a1r : a0r;  Ci = ic ? a1i : a0i; }
            else             { Dr = id_ ? a1r : a0r; Di = id_ ? a1i : a0i; }
        }
    }
    u64 zr, zi;
    {
        float cdr = Cr * Dr - Ci * Di;
        float cdi = Cr * Di + Ci * Dr;
        float BLr = r1 ? B1r : B0r, BLi = r1 ? B1i : B0i;   // B(0^r1)
        float BHr = r1 ? B0r : B1r, BHi = r1 ? B0i : B1i;   // B(1^r1)
        float tlr = A0r * BLr - A0i * BLi;
        float tli = A0r * BLi + A0i * BLr;
        float thr = A1r * BHr - A1i * BHi;
        float thi = A1r * BHi + A1i * BHr;
        float zlr = tlr * cdr - tli * cdi;
        float zli = tlr * cdi + tli * cdr;
        float zhr = thr * cdr - thi * cdi;
        float zhi = thr * cdi + thi * cdr;
        zr = pk2(zlr, zhr);
        zi = pk2(zli, zhi);
    }

    // ---- layers 1..4
#pragma unroll
    for (int li = 0; li < 4; li++) {
        // G0' on q0 (pack dim)
        {
            const u64* c = cG0[li][r3];
            u64 sr = swap2(zr), si = swap2(zi);
            u64 nre = fma2_(c[3], si, fma2_(c[2], sr, fma2_(c[1], zi, mul2_(c[0], zr))));
            u64 nim = fma2_(c[2], si, fma2_(c[5], sr, fma2_(c[0], zi, mul2_(c[4], zr))));
            zr = nre; zi = nim;
        }
        // G1' on q1 (xor 4); X01 fold lives in the hi halves of the bank
        {
            const u64* c = cG1[li][r1];
            u64 pr = __shfl_xor_sync(0xffffffffu, zr, 4);
            u64 pi = __shfl_xor_sync(0xffffffffu, zi, 4);
            u64 nre = fma2_(c[4], pi, fma2_(c[3], pr, fma2_(c[1], zi, mul2_(c[0], zr))));
            u64 nim = fma2_(c[5], pr, fma2_(c[3], pi, fma2_(c[2], zr, mul2_(c[0], zi))));
            zr = nre; zi = nim;
        }
        // G2' on q2 (xor 2)
        {
            const u64* c = cG2[li][r1 * 2 + r2];
            u64 pr = __shfl_xor_sync(0xffffffffu, zr, 2);
            u64 pi = __shfl_xor_sync(0xffffffffu, zi, 2);
            u64 nre = fma2_(c[4], pi, fma2_(c[3], pr, fma2_(c[1], zi, mul2_(c[0], zr))));
            u64 nim = fma2_(c[5], pr, fma2_(c[3], pi, fma2_(c[2], zr, mul2_(c[0], zi))));
            zr = nre; zi = nim;
        }
        // G3' on q3 (xor 1)
        {
            const u64* c = cG3[li][r2 * 2 + r3];
            u64 pr = __shfl_xor_sync(0xffffffffu, zr, 1);
            u64 pi = __shfl_xor_sync(0xffffffffu, zi, 1);
            u64 nre = fma2_(c[4], pi, fma2_(c[3], pr, fma2_(c[1], zi, mul2_(c[0], zr))));
            u64 nim = fma2_(c[5], pr, fma2_(c[3], pi, fma2_(c[2], zr, mul2_(c[0], zi))));
            zr = nre; zi = nim;
        }
    }

    // ---- <Z_q> partials + octet reduction
    {
        u64 s2 = fma2_(zr, zr, mul2_(zi, zi));
        float plo, phi;
        upk2(plo, phi, s2);
        float S  = plo + phi;
        float e0 = plo - phi;
        float e1 = r1 ? -S : S;
        float e2 = r2 ? -S : S;
        float e3 = r3 ? -S : S;
#pragma unroll
        for (int off = 1; off <= 4; off <<= 1) {
            e0 += __shfl_xor_sync(0xffffffffu, e0, off);
            e1 += __shfl_xor_sync(0xffffffffu, e1, off);
            e2 += __shfl_xor_sync(0xffffffffu, e2, off);
            e3 += __shfl_xor_sync(0xffffffffu, e3, off);
        }
        if (valid && sub < 4) {
            float val = (sub == 0) ? e0 : (sub == 1) ? e1 : (sub == 2) ? e2 : e3;
            g_feat[gp * 4 + sub] = val;
        }
    }
}

// ============================ Kernel B: MLP ============================
#define NWARPS_B 16
__global__ __launch_bounds__(512)
void mlp_kernel(const float* __restrict__ fc1_w,   // [64,784]
                const float* __restrict__ fc1_b,   // [64]
                const float* __restrict__ fc2_w,   // [10,64]
                const float* __restrict__ fc2_b,   // [10]
                float* __restrict__ out)           // [B,10]
{
    __shared__ __align__(16) float sfeat[784];
    __shared__ float hidden[64];

    const int b   = blockIdx.x;
    const int tid = threadIdx.x;

    for (int i = tid; i < 784; i += 512)
        sfeat[i] = g_feat[b * 784 + i];
    __syncthreads();

    {
        const int warp = tid >> 5;
        const int lane = tid & 31;
        const u64* F2 = reinterpret_cast<const u64*>(sfeat);
        for (int h = warp; h < 64; h += NWARPS_B) {
            u64 acc2 = 0ull;
            for (int kk = lane; kk < 196; kk += 32) {
                const ulonglong2 wv =
                    *reinterpret_cast<const ulonglong2*>(fc1_w + (h * 196 + kk) * 4);
                acc2 = fma2_(wv.x, F2[2 * kk],     acc2);
                acc2 = fma2_(wv.y, F2[2 * kk + 1], acc2);
            }
            float alo, ahi;
            upk2(alo, ahi, acc2);
            float acc = alo + ahi;
#pragma unroll
            for (int off = 16; off; off >>= 1)
                acc += __shfl_down_sync(0xffffffffu, acc, off);
            if (lane == 0)
                hidden[h] = fmaxf(acc + fc1_b[h], 0.f);
        }
    }
    __syncthreads();

    if (tid < 10) {
        float acc = fc2_b[tid];
#pragma unroll 8
        for (int h = 0; h < 64; h++)
            acc += hidden[h] * fc2_w[tid * 64 + h];
        out[b * 10 + tid] = acc;
    }
}

extern "C" void kernel_launch(void* const* d_in, const int* in_sizes, int n_in,
                              void* d_out, int out_size) {
    const float* x     = (const float*)d_in[0];
    const float* w     = (const float*)d_in[1];
    const float* fc1_w = (const float*)d_in[2];
    const float* fc1_b = (const float*)d_in[3];
    const float* fc2_w = (const float*)d_in[4];
    const float* fc2_b = (const float*)d_in[5];
    float* out = (float*)d_out;

    const int B = in_sizes[0] / 784;            // 128
    const int total_patches = B * 196;          // 25088
    const int blocksA = (total_patches * 8 + 511) / 512;   // 392
    qcirc_kernel<<<blocksA, 512>>>(x, w, total_patches);
    mlp_kernel<<<B, 512>>>(fc1_w, fc1_b, fc2_w, fc2_b, out);
}